// round 15
// baseline (speedup 1.0000x reference)
#include <cuda_runtime.h>
#include <cstddef>
#include <cstdint>

// FastNGramLM advance, round 15: one-shot blocks, two 32KB TMA copies,
// DYNAMIC shared memory (static smem is capped at 48KB; we need 64KB).
//  - HPB=8, TPB=256, grid=1024. Each block's output rows are CONTIGUOUS:
//    scores[h0*V..(h0+8)*V) and next[h0*V..(h0+8)*V), 32KB each.
//  - stage the block's ENTIRE output in smem, patch all overlay slots in
//    smem (chain records live in the chain threads' registers), then tid0
//    ships exactly TWO cp.async.bulk copies.
//  - 3 __syncthreads per block TOTAL; only tid0 waits for TMA smem reads.
//
// Output: d_out[0..B*V) = scores f32, d_out[B*V..2BV) = next as exact f32.

#define VMAX  1024
#define DEPTH 3
#define ARCS  16
#define HPB   8
#define TPB   256

__device__ __forceinline__ uint32_t smem_u32(const void* p) {
    return (uint32_t)__cvta_generic_to_shared(p);
}

__global__ __launch_bounds__(TPB)
void ngram_fused_kernel(const float* __restrict__ arcs_weights,
                        const float* __restrict__ backoff_weights,
                        const int*   __restrict__ ilabels,
                        const int*   __restrict__ to_states,
                        const int*   __restrict__ backoff_to,
                        const int*   __restrict__ state_start,
                        const int*   __restrict__ state_end,
                        const int*   __restrict__ states,
                        float*       __restrict__ out_scores,
                        float*       __restrict__ out_next,
                        int B, int V)
{
    extern __shared__ __align__(128) float smem[];
    float* s_sc = smem;                    // [HPB*VMAX] score rows (32KB)
    float* s_nx = smem + HPB * VMAX;       // [HPB*VMAX] next rows  (32KB)
    __shared__ float s_acc[HPB];

    const int tid = threadIdx.x;
    const int h0  = blockIdx.x * HPB;

    // ---- dense fallback -> registers ----
    const float4 wf  = __ldg((const float4*)arcs_weights + tid);
    const int4   nfi = __ldg((const int4*)  to_states    + tid);
    float4 nfv;
    nfv.x = (float)nfi.x; nfv.y = (float)nfi.y;
    nfv.z = (float)nfi.z; nfv.w = (float)nfi.w;

    // ---- chain phase: threads 0..127 = 8 hyps x 16 lanes, regs-resident ----
    int   lab[DEPTH];
    float scr[DEPTH];
    float nxf[DEPTH];
    const int jh = tid >> 4;           // hypothesis slot for chain/patch
    if (tid < HPB * ARCS) {
        const int lane = tid & 15;
        const int h    = h0 + jh;
        int   cur = (h < B) ? __ldg(&states[h]) : 0;
        float acc = 0.0f;
        #pragma unroll
        for (int d = 0; d < DEPTH; ++d) {
            lab[d] = -1; scr[d] = 0.0f; nxf[d] = 0.0f;
            if (cur != 0) {                    // START == 0
                const int st  = __ldg(&state_start[cur]);
                const int en  = __ldg(&state_end[cur]);
                const int idx = st + lane;
                if (idx < en) {
                    lab[d] = __ldg(&ilabels[idx]);
                    scr[d] = acc + __ldg(&arcs_weights[idx]);
                    nxf[d] = (float)__ldg(&to_states[idx]);
                }
                acc += __ldg(&backoff_weights[cur]);
                cur  = __ldg(&backoff_to[cur]);
            }
        }
        if (lane == 0) s_acc[jh] = acc;
    }
    __syncthreads();   // s_acc ready                                   [1]

    // ---- build ALL rows: 8 score rows + 8 next rows ----
    const int lab0 = tid * 4;
    #pragma unroll
    for (int j = 0; j < HPB; ++j) {
        const float acc = s_acc[j];
        float4 sc;
        sc.x = acc + wf.x; sc.y = acc + wf.y;
        sc.z = acc + wf.z; sc.w = acc + wf.w;
        *(float4*)&s_sc[j * VMAX + lab0] = sc;
        *(float4*)&s_nx[j * VMAX + lab0] = nfv;
    }
    __syncthreads();   // staging complete, visible to patchers         [2]

    // ---- patch all overlays in smem (threads 0..127, regs-resident) ----
    if (tid < HPB * ARCS) {            // warp-uniform (tid < 128)
        const int rowoff = jh * VMAX;
        #pragma unroll
        for (int d = DEPTH - 1; d >= 0; --d) {   // shallow lands last
            if (lab[d] >= 0) {
                s_sc[rowoff + lab[d]] = scr[d];
                s_nx[rowoff + lab[d]] = nxf[d];
            }
            __syncwarp();              // order depth rounds
        }
    }
    __syncthreads();   // patches visible to the shipping thread        [3]

    // ---- ship: two 32KB bulk copies; only tid0 waits ----
    if (tid == 0) {
        asm volatile("fence.proxy.async.shared::cta;" ::: "memory");
        const size_t g = (size_t)h0 * (size_t)V;
        const int    nrows = (h0 + HPB <= B) ? HPB : (B - h0);
        const int    bytes = nrows * VMAX * 4;
        asm volatile(
            "cp.async.bulk.global.shared::cta.bulk_group [%0], [%1], %2;"
            :: "l"(out_scores + g), "r"(smem_u32(s_sc)), "r"(bytes) : "memory");
        asm volatile(
            "cp.async.bulk.global.shared::cta.bulk_group [%0], [%1], %2;"
            :: "l"(out_next + g), "r"(smem_u32(s_nx)), "r"(bytes) : "memory");
        asm volatile("cp.async.bulk.commit_group;" ::: "memory");
        // smem-reuse safety: TMA must finish READING smem before this CTA's
        // smem can be handed to a successor. Other warps may retire freely.
        asm volatile("cp.async.bulk.wait_group.read 0;" ::: "memory");
    }
}

extern "C" void kernel_launch(void* const* d_in, const int* in_sizes, int n_in,
                              void* d_out, int out_size)
{
    // Classify inputs by element count (robust to metadata ordering):
    //   arcs group (3x largest):  arcs_weights, ilabels, to_states
    //   state group (4x middle):  backoff_weights, backoff_to, start, end
    //   states: the remaining batch-sized array
    long long max_sz = 0;
    for (int i = 0; i < n_in; ++i)
        if ((long long)in_sizes[i] > max_sz) max_sz = in_sizes[i];

    long long arc_sz = max_sz;
    long long n_sz = -1;
    for (int i = 0; i < n_in; ++i) {
        int cnt = 0;
        for (int j = 0; j < n_in; ++j)
            if (in_sizes[j] == in_sizes[i]) ++cnt;
        if (cnt == 4) { n_sz = in_sizes[i]; break; }
    }

    const void* arc_grp[3];  int na = 0;
    const void* st_grp[4];   int ns = 0;
    const void* states_ptr = nullptr;
    long long B = 0;
    for (int i = 0; i < n_in; ++i) {
        if (in_sizes[i] == arc_sz && na < 3)      arc_grp[na++] = d_in[i];
        else if (in_sizes[i] == n_sz && ns < 4)   st_grp[ns++]  = d_in[i];
        else { states_ptr = d_in[i]; B = in_sizes[i]; }
    }

    const float* arcs_weights    = (const float*)arc_grp[0];
    const int*   ilabels         = (const int*)  arc_grp[1];
    const int*   to_states       = (const int*)  arc_grp[2];
    const float* backoff_weights = (const float*)st_grp[0];
    const int*   backoff_to      = (const int*)  st_grp[1];
    const int*   state_start     = (const int*)  st_grp[2];
    const int*   state_end       = (const int*)  st_grp[3];
    const int*   states          = (const int*)  states_ptr;

    const long long V = (long long)out_size / (2 * B);
    float* out_scores = (float*)d_out;
    float* out_next   = (float*)d_out + (size_t)B * (size_t)V;

    const size_t smem_bytes = (size_t)2 * HPB * VMAX * sizeof(float);  // 64KB
    // Opt in to >48KB dynamic smem (attribute set, not an allocation;
    // immediate host-side call, safe under graph capture).
    cudaFuncSetAttribute(ngram_fused_kernel,
                         cudaFuncAttributeMaxDynamicSharedMemorySize,
                         (int)smem_bytes);

    const int grid = (int)((B + HPB - 1) / HPB);
    ngram_fused_kernel<<<grid, TPB, smem_bytes>>>(
        arcs_weights, backoff_weights, ilabels, to_states,
        backoff_to, state_start, state_end, states,
        out_scores, out_next, (int)B, (int)V);
}

// round 16
// speedup vs baseline: 1.2929x; 1.2929x over previous
#include <cuda_runtime.h>
#include <cstddef>
#include <cstdint>

// FastNGramLM advance, round 16: R9 refined.
//  - 256 thr, HPB=8, grid=1024, single wave, 8 CTAs/SM (thread-limited)
//  - chain records -> smem (written once); warp 0 BOTH patches and ships
//    (tid0's per-thread bulk-group state stays consistent) -> 2 barriers/hyp
//  - NBUF=3 staging buffers (24KB) + wait_group.read 2 -> two groups of
//    slack, the wait almost never blocks
//
// Output: d_out[0..B*V) = scores f32, d_out[B*V..2BV) = next as exact f32.

#define VMAX  1024
#define DEPTH 3
#define ARCS  16
#define HPB   8
#define TPB   256
#define NBUF  3

__device__ __forceinline__ uint32_t smem_u32(const void* p) {
    return (uint32_t)__cvta_generic_to_shared(p);
}

__global__ __launch_bounds__(TPB, 8)
void ngram_fused_kernel(const float* __restrict__ arcs_weights,
                        const float* __restrict__ backoff_weights,
                        const int*   __restrict__ ilabels,
                        const int*   __restrict__ to_states,
                        const int*   __restrict__ backoff_to,
                        const int*   __restrict__ state_start,
                        const int*   __restrict__ state_end,
                        const int*   __restrict__ states,
                        float*       __restrict__ out_scores,
                        float*       __restrict__ out_next,
                        int B, int V)
{
    __shared__ __align__(128) float s_sc[NBUF][VMAX];   // staging: scores
    __shared__ __align__(128) float s_nx[NBUF][VMAX];   // staging: next rows
    __shared__ int   s_lab[HPB][DEPTH][ARCS];
    __shared__ float s_scr[HPB][DEPTH][ARCS];
    __shared__ float s_nxt[HPB][DEPTH][ARCS];
    __shared__ float s_acc[HPB];

    const int tid  = threadIdx.x;
    const int w    = tid >> 5;
    const int lane = tid & 31;
    const int h0   = blockIdx.x * HPB;

    // ---- dense fallback -> registers ----
    const float4 wf  = __ldg((const float4*)arcs_weights + tid);
    const int4   nfi = __ldg((const int4*)  to_states    + tid);
    float4 nfv;
    nfv.x = (float)nfi.x; nfv.y = (float)nfi.y;
    nfv.z = (float)nfi.z; nfv.w = (float)nfi.w;

    // ---- chain phase: threads 0..127 = 8 hyps x 16 lanes -> smem records ----
    if (tid < HPB * ARCS) {
        const int j  = tid >> 4;
        const int ln = tid & 15;
        const int h  = h0 + j;
        int   cur = (h < B) ? __ldg(&states[h]) : 0;
        float acc = 0.0f;
        #pragma unroll
        for (int d = 0; d < DEPTH; ++d) {
            int lb = -1; float sv = 0.0f, nv = 0.0f;
            if (cur != 0) {                    // START == 0
                const int st  = __ldg(&state_start[cur]);
                const int en  = __ldg(&state_end[cur]);
                const int idx = st + ln;
                if (idx < en) {
                    lb = __ldg(&ilabels[idx]);
                    sv = acc + __ldg(&arcs_weights[idx]);
                    nv = (float)__ldg(&to_states[idx]);
                }
                acc += __ldg(&backoff_weights[cur]);
                cur  = __ldg(&backoff_to[cur]);
            }
            s_lab[j][d][ln] = lb;
            s_scr[j][d][ln] = sv;
            s_nxt[j][d][ln] = nv;
        }
        if (ln == 0) s_acc[j] = acc;
    }
    __syncthreads();   // records + acc ready

    const int lab0 = tid * 4;
    int p = 0;   // staging buffer index, cycles 0,1,2

    for (int j = 0; j < HPB; ++j) {
        const int h = h0 + j;

        // ---- all threads: build buffer p (score row + next row) ----
        {
            const float acc = s_acc[j];
            float4 sc;
            sc.x = acc + wf.x; sc.y = acc + wf.y;
            sc.z = acc + wf.z; sc.w = acc + wf.w;
            *(float4*)&s_sc[p][lab0] = sc;
            *(float4*)&s_nx[p][lab0] = nfv;
        }
        __syncthreads();   // build visible to warp 0                   [1]

        // ---- warp 0: patch both rows, then lane 0 ships ----
        if (w == 0) {
            #pragma unroll
            for (int d = DEPTH - 1; d >= 0; --d) {   // shallow lands last
                if (lane < ARCS) {
                    const int lb = s_lab[j][d][lane];
                    if (lb >= 0) {
                        s_sc[p][lb] = s_scr[j][d][lane];
                        s_nx[p][lb] = s_nxt[j][d][lane];
                    }
                }
                __syncwarp();          // order depth rounds
            }
            if (lane == 0 && h < B) {
                asm volatile("fence.proxy.async.shared::cta;" ::: "memory");
                const size_t   g   = (size_t)h * (size_t)V;
                const uint32_t ssc = smem_u32(&s_sc[p][0]);
                const uint32_t snx = smem_u32(&s_nx[p][0]);
                asm volatile(
                    "cp.async.bulk.global.shared::cta.bulk_group [%0], [%1], %2;"
                    :: "l"(out_scores + g), "r"(ssc), "r"(V * 4) : "memory");
                asm volatile(
                    "cp.async.bulk.global.shared::cta.bulk_group [%0], [%1], %2;"
                    :: "l"(out_next + g), "r"(snx), "r"(V * 4) : "memory");
                asm volatile("cp.async.bulk.commit_group;" ::: "memory");
                // two groups of slack: groups <= j-2 have finished READING
                // smem -> buffer reused at j+3 is safe after next barrier
                asm volatile("cp.async.bulk.wait_group.read 2;" ::: "memory");
            }
        }
        __syncthreads();   // ship issued; reuse-safety published        [2]

        p = (p == NBUF - 1) ? 0 : p + 1;
    }
}

extern "C" void kernel_launch(void* const* d_in, const int* in_sizes, int n_in,
                              void* d_out, int out_size)
{
    // Classify inputs by element count (robust to metadata ordering):
    //   arcs group (3x largest):  arcs_weights, ilabels, to_states
    //   state group (4x middle):  backoff_weights, backoff_to, start, end
    //   states: the remaining batch-sized array
    long long max_sz = 0;
    for (int i = 0; i < n_in; ++i)
        if ((long long)in_sizes[i] > max_sz) max_sz = in_sizes[i];

    long long arc_sz = max_sz;
    long long n_sz = -1;
    for (int i = 0; i < n_in; ++i) {
        int cnt = 0;
        for (int j = 0; j < n_in; ++j)
            if (in_sizes[j] == in_sizes[i]) ++cnt;
        if (cnt == 4) { n_sz = in_sizes[i]; break; }
    }

    const void* arc_grp[3];  int na = 0;
    const void* st_grp[4];   int ns = 0;
    const void* states_ptr = nullptr;
    long long B = 0;
    for (int i = 0; i < n_in; ++i) {
        if (in_sizes[i] == arc_sz && na < 3)      arc_grp[na++] = d_in[i];
        else if (in_sizes[i] == n_sz && ns < 4)   st_grp[ns++]  = d_in[i];
        else { states_ptr = d_in[i]; B = in_sizes[i]; }
    }

    const float* arcs_weights    = (const float*)arc_grp[0];
    const int*   ilabels         = (const int*)  arc_grp[1];
    const int*   to_states       = (const int*)  arc_grp[2];
    const float* backoff_weights = (const float*)st_grp[0];
    const int*   backoff_to      = (const int*)  st_grp[1];
    const int*   state_start     = (const int*)  st_grp[2];
    const int*   state_end       = (const int*)  st_grp[3];
    const int*   states          = (const int*)  states_ptr;

    const long long V = (long long)out_size / (2 * B);
    float* out_scores = (float*)d_out;
    float* out_next   = (float*)d_out + (size_t)B * (size_t)V;

    const int grid = (int)((B + HPB - 1) / HPB);
    ngram_fused_kernel<<<grid, TPB>>>(
        arcs_weights, backoff_weights, ilabels, to_states,
        backoff_to, state_start, state_end, states,
        out_scores, out_next, (int)B, (int)V);
}